// round 1
// baseline (speedup 1.0000x reference)
#include <cuda_runtime.h>

#define BATCH 4096
#define T_STEPS 50
#define HID 256
#define HSTR (T_STEPS * HID)   // row stride of out: 12800 floats

// ---------------- scratch (no allocations allowed) ----------------
__device__ float g_h1[BATCH * 512];
__device__ float g_h2[BATCH * 256];
__device__ float g_z [BATCH * 128];
__device__ float g_xp[BATCH * 1024];
__device__ float g_c [BATCH * 256];

// ---------------- helpers ----------------
__device__ __forceinline__ float sigmoidf_fast(float x) {
    return 1.0f / (1.0f + __expf(-x));
}
__device__ __forceinline__ float tanhf_fast(float x) {
    return 2.0f / (1.0f + __expf(-2.0f * x)) - 1.0f;
}
__device__ __forceinline__ unsigned long long pack2(float a, float b) {
    unsigned long long r;
    asm("mov.b64 %0, {%1, %2};" : "=l"(r) : "f"(a), "f"(b));
    return r;
}
__device__ __forceinline__ void unpack2(unsigned long long v, float& a, float& b) {
    asm("mov.b64 {%0, %1}, %2;" : "=f"(a), "=f"(b) : "l"(v));
}
// packed dual-fp32 FMA (Blackwell f32x2 pipe, 2x scalar FFMA throughput)
__device__ __forceinline__ void ffma2(unsigned long long& d,
                                      unsigned long long a,
                                      unsigned long long b) {
    asm("fma.rn.f32x2 %0, %1, %2, %3;" : "=l"(d) : "l"(a), "l"(b), "l"(d));
}

// ---------------- generic C = act(A @ W^T + bias [+bias2]) ----------------
// A: [M,K] row-major, W: [N,K] row-major. BM=BN=64, BK=16, 256 threads, 4x4 microtile.
__global__ void __launch_bounds__(256) gemm_bias_kernel(
    const float* __restrict__ A, const float* __restrict__ W,
    const float* __restrict__ bias, const float* __restrict__ bias2,
    float* __restrict__ C, int M, int N, int K, int relu)
{
    __shared__ __align__(16) float As[16][68];
    __shared__ __align__(16) float Ws[16][68];
    const int tid = threadIdx.x;
    const int bm = blockIdx.y << 6;
    const int bn = blockIdx.x << 6;
    const int lr = tid >> 2;          // 0..63
    const int lc = (tid & 3) << 2;    // 0,4,8,12
    const int m0 = (tid >> 4) << 2;   // 0..60
    const int n0 = (tid & 15) << 2;   // 0..60

    float acc[4][4] = {};

    for (int k0 = 0; k0 < K; k0 += 16) {
        float4 av = *(const float4*)(A + (size_t)(bm + lr) * K + k0 + lc);
        float4 wv = *(const float4*)(W + (size_t)(bn + lr) * K + k0 + lc);
        As[lc + 0][lr] = av.x; As[lc + 1][lr] = av.y;
        As[lc + 2][lr] = av.z; As[lc + 3][lr] = av.w;
        Ws[lc + 0][lr] = wv.x; Ws[lc + 1][lr] = wv.y;
        Ws[lc + 2][lr] = wv.z; Ws[lc + 3][lr] = wv.w;
        __syncthreads();
        #pragma unroll
        for (int k = 0; k < 16; k++) {
            float4 a4 = *(const float4*)&As[k][m0];
            float4 b4 = *(const float4*)&Ws[k][n0];
            float a[4] = {a4.x, a4.y, a4.z, a4.w};
            float b[4] = {b4.x, b4.y, b4.z, b4.w};
            #pragma unroll
            for (int i = 0; i < 4; i++)
                #pragma unroll
                for (int j = 0; j < 4; j++)
                    acc[i][j] = fmaf(a[i], b[j], acc[i][j]);
        }
        __syncthreads();
    }

    #pragma unroll
    for (int j = 0; j < 4; j++) {
        float bv = bias[bn + n0 + j];
        if (bias2) bv += bias2[bn + n0 + j];
        #pragma unroll
        for (int i = 0; i < 4; i++) {
            float v = acc[i][j] + bv;
            if (relu) v = fmaxf(v, 0.0f);
            C[(size_t)(bm + m0 + i) * N + (bn + n0 + j)] = v;
        }
    }
}

// ---------------- fused LSTM step ----------------
// Computes gates = x_part + h_{t-1} @ W_hh^T for a 64x32 tile of (batch, hidden),
// then the LSTM cell update, writing h_t directly into out[:, t, :].
// h_{t-1} is read from out[:, t-1, :]. Packed f32x2 accumulation over row pairs.
__global__ void __launch_bounds__(256) lstm_step_kernel(
    const float* __restrict__ xp,     // [B, 1024] precomputed input part
    const float* __restrict__ Whh,    // [1024, 256]
    float* __restrict__ out,          // [B, T, H]
    float* __restrict__ c,            // [B, H] cell state
    int t)
{
    __shared__ __align__(16) float hs[32][66];       // [k][row], padded
    __shared__ __align__(16) float ws[4][32][33];    // [gate][k][j], padded

    const int tid = threadIdx.x;
    const int tx = tid & 31;        // j within tile
    const int ty = tid >> 5;        // row-group (8 rows each)
    const int bm = blockIdx.y << 6; // batch tile base
    const int jb = blockIdx.x << 5; // hidden-col tile base

    unsigned long long acc[4][4];   // [row-pair][gate] packed f32x2
    #pragma unroll
    for (int p = 0; p < 4; p++)
        #pragma unroll
        for (int g = 0; g < 4; g++) acc[p][g] = 0ULL;

    if (t > 0) {
        const float* hprev = out + (size_t)(t - 1) * HID;
        const int wj = tid >> 3;             // 0..31
        const int wk = (tid & 7) << 2;       // 0,4,...,28
        for (int k0 = 0; k0 < HID; k0 += 32) {
            // h tile: 64 rows x 32 k
            #pragma unroll
            for (int q = 0; q < 2; q++) {
                int i4 = q * 256 + tid;
                int row = i4 >> 3;
                int kq = (i4 & 7) << 2;
                float4 v = *(const float4*)(hprev + (size_t)(bm + row) * HSTR + k0 + kq);
                hs[kq + 0][row] = v.x; hs[kq + 1][row] = v.y;
                hs[kq + 2][row] = v.z; hs[kq + 3][row] = v.w;
            }
            // W tiles: 4 gates x 32 j x 32 k
            #pragma unroll
            for (int g = 0; g < 4; g++) {
                float4 v = *(const float4*)(Whh + (size_t)(g * 256 + jb + wj) * HID + k0 + wk);
                ws[g][wk + 0][wj] = v.x; ws[g][wk + 1][wj] = v.y;
                ws[g][wk + 2][wj] = v.z; ws[g][wk + 3][wj] = v.w;
            }
            __syncthreads();
            #pragma unroll
            for (int k = 0; k < 32; k++) {
                unsigned long long w2[4], h2[4];
                #pragma unroll
                for (int g = 0; g < 4; g++) {
                    float wv = ws[g][k][tx];
                    w2[g] = pack2(wv, wv);
                }
                #pragma unroll
                for (int p = 0; p < 4; p++)
                    h2[p] = *(const unsigned long long*)&hs[k][ty * 8 + p * 2];
                #pragma unroll
                for (int p = 0; p < 4; p++)
                    #pragma unroll
                    for (int g = 0; g < 4; g++)
                        ffma2(acc[p][g], h2[p], w2[g]);
            }
            __syncthreads();
        }
    }

    // epilogue: LSTM cell
    const int col = jb + tx;
    #pragma unroll
    for (int p = 0; p < 4; p++) {
        float lo[4], hi[4];
        #pragma unroll
        for (int g = 0; g < 4; g++) unpack2(acc[p][g], lo[g], hi[g]);
        #pragma unroll
        for (int rr = 0; rr < 2; rr++) {
            const float* gv = rr ? hi : lo;
            const int row = bm + ty * 8 + p * 2 + rr;
            const size_t xb = (size_t)row * 1024 + col;
            float vi = sigmoidf_fast(gv[0] + xp[xb]);
            float vf = sigmoidf_fast(gv[1] + xp[xb + 256]);
            float vg = tanhf_fast  (gv[2] + xp[xb + 512]);
            float vo = sigmoidf_fast(gv[3] + xp[xb + 768]);
            float cp = (t == 0) ? 0.0f : c[(size_t)row * HID + col];
            float cn = vf * cp + vi * vg;
            c[(size_t)row * HID + col] = cn;
            out[(size_t)row * HSTR + (size_t)t * HID + col] = vo * tanhf_fast(cn);
        }
    }
}

// ---------------- launch ----------------
extern "C" void kernel_launch(void* const* d_in, const int* in_sizes, int n_in,
                              void* d_out, int out_size)
{
    const float* zs  = (const float*)d_in[0];
    const float* W1  = (const float*)d_in[1];
    const float* b1  = (const float*)d_in[2];
    const float* W2  = (const float*)d_in[3];
    const float* b2  = (const float*)d_in[4];
    const float* W3  = (const float*)d_in[5];
    const float* b3  = (const float*)d_in[6];
    const float* Wih = (const float*)d_in[7];
    const float* Whh = (const float*)d_in[8];
    const float* bih = (const float*)d_in[9];
    const float* bhh = (const float*)d_in[10];
    float* out = (float*)d_out;

    float *h1, *h2, *z, *xpv, *cv;
    cudaGetSymbolAddress((void**)&h1,  g_h1);
    cudaGetSymbolAddress((void**)&h2,  g_h2);
    cudaGetSymbolAddress((void**)&z,   g_z);
    cudaGetSymbolAddress((void**)&xpv, g_xp);
    cudaGetSymbolAddress((void**)&cv,  g_c);

    // MLP: h1 = relu(zs@W1^T+b1); h2 = relu(h1@W2^T+b2); z = h2@W3^T+b3
    gemm_bias_kernel<<<dim3(512 / 64,  BATCH / 64), 256>>>(zs, W1, b1, nullptr, h1, BATCH, 512, 256, 1);
    gemm_bias_kernel<<<dim3(256 / 64,  BATCH / 64), 256>>>(h1, W2, b2, nullptr, h2, BATCH, 256, 512, 1);
    gemm_bias_kernel<<<dim3(128 / 64,  BATCH / 64), 256>>>(h2, W3, b3, nullptr, z,  BATCH, 128, 256, 0);
    // x_part = z@W_ih^T + b_ih + b_hh
    gemm_bias_kernel<<<dim3(1024 / 64, BATCH / 64), 256>>>(z, Wih, bih, bhh, xpv, BATCH, 1024, 128, 0);

    // 50 fused LSTM steps
    for (int t = 0; t < T_STEPS; t++)
        lstm_step_kernel<<<dim3(HID / 32, BATCH / 64), 256>>>(xpv, Whh, out, cv, t);
}

// round 2
// speedup vs baseline: 1.0021x; 1.0021x over previous
#include <cuda_runtime.h>

#define BATCH 4096
#define T_STEPS 50
#define HID 256
#define HSTR (T_STEPS * HID)   // row stride of out: 12800 floats

// ---------------- scratch (no allocations allowed) ----------------
__device__ float g_h1[BATCH * 512];
__device__ float g_h2[BATCH * 256];
__device__ float g_z [BATCH * 128];
__device__ float g_xp[BATCH * 1024];
__device__ float g_c [BATCH * 256];

// ---------------- helpers ----------------
__device__ __forceinline__ float sigmoidf_fast(float x) {
    return 1.0f / (1.0f + __expf(-x));
}
__device__ __forceinline__ float tanhf_fast(float x) {
    return 2.0f / (1.0f + __expf(-2.0f * x)) - 1.0f;
}
__device__ __forceinline__ unsigned long long pack2(float a, float b) {
    unsigned long long r;
    asm("mov.b64 %0, {%1, %2};" : "=l"(r) : "f"(a), "f"(b));
    return r;
}
__device__ __forceinline__ void unpack2(unsigned long long v, float& a, float& b) {
    asm("mov.b64 {%0, %1}, %2;" : "=f"(a), "=f"(b) : "l"(v));
}
// packed dual-fp32 FMA (Blackwell f32x2 pipe, 2x scalar FFMA throughput)
__device__ __forceinline__ void ffma2(unsigned long long& d,
                                      unsigned long long a,
                                      unsigned long long b) {
    asm("fma.rn.f32x2 %0, %1, %2, %3;" : "=l"(d) : "l"(a), "l"(b), "l"(d));
}

// ---------------- generic C = act(A @ W^T + bias [+bias2]) ----------------
// A: [M,K] row-major, W: [N,K] row-major. BM=BN=64, BK=16, 256 threads, 4x4 microtile.
__global__ void __launch_bounds__(256) gemm_bias_kernel(
    const float* __restrict__ A, const float* __restrict__ W,
    const float* __restrict__ bias, const float* __restrict__ bias2,
    float* __restrict__ C, int M, int N, int K, int relu)
{
    __shared__ __align__(16) float As[16][68];
    __shared__ __align__(16) float Ws[16][68];
    const int tid = threadIdx.x;
    const int bm = blockIdx.y << 6;
    const int bn = blockIdx.x << 6;
    const int lr = tid >> 2;          // 0..63
    const int lc = (tid & 3) << 2;    // 0,4,8,12
    const int m0 = (tid >> 4) << 2;   // 0..60
    const int n0 = (tid & 15) << 2;   // 0..60

    float acc[4][4] = {};

    for (int k0 = 0; k0 < K; k0 += 16) {
        float4 av = *(const float4*)(A + (size_t)(bm + lr) * K + k0 + lc);
        float4 wv = *(const float4*)(W + (size_t)(bn + lr) * K + k0 + lc);
        As[lc + 0][lr] = av.x; As[lc + 1][lr] = av.y;
        As[lc + 2][lr] = av.z; As[lc + 3][lr] = av.w;
        Ws[lc + 0][lr] = wv.x; Ws[lc + 1][lr] = wv.y;
        Ws[lc + 2][lr] = wv.z; Ws[lc + 3][lr] = wv.w;
        __syncthreads();
        #pragma unroll
        for (int k = 0; k < 16; k++) {
            float4 a4 = *(const float4*)&As[k][m0];
            float4 b4 = *(const float4*)&Ws[k][n0];
            float a[4] = {a4.x, a4.y, a4.z, a4.w};
            float b[4] = {b4.x, b4.y, b4.z, b4.w};
            #pragma unroll
            for (int i = 0; i < 4; i++)
                #pragma unroll
                for (int j = 0; j < 4; j++)
                    acc[i][j] = fmaf(a[i], b[j], acc[i][j]);
        }
        __syncthreads();
    }

    #pragma unroll
    for (int j = 0; j < 4; j++) {
        float bv = bias[bn + n0 + j];
        if (bias2) bv += bias2[bn + n0 + j];
        #pragma unroll
        for (int i = 0; i < 4; i++) {
            float v = acc[i][j] + bv;
            if (relu) v = fmaxf(v, 0.0f);
            C[(size_t)(bm + m0 + i) * N + (bn + n0 + j)] = v;
        }
    }
}

// ---------------- fused LSTM step ----------------
// Computes gates = x_part + h_{t-1} @ W_hh^T for a 64x32 tile of (batch, hidden),
// then the LSTM cell update, writing h_t directly into out[:, t, :].
// h_{t-1} is read from out[:, t-1, :]. Packed f32x2 accumulation over row pairs.
__global__ void __launch_bounds__(256) lstm_step_kernel(
    const float* __restrict__ xp,     // [B, 1024] precomputed input part
    const float* __restrict__ Whh,    // [1024, 256]
    float* __restrict__ out,          // [B, T, H]
    float* __restrict__ c,            // [B, H] cell state
    int t)
{
    __shared__ __align__(16) float hs[32][66];       // [k][row], padded
    __shared__ __align__(16) float ws[4][32][33];    // [gate][k][j], padded

    const int tid = threadIdx.x;
    const int tx = tid & 31;        // j within tile
    const int ty = tid >> 5;        // row-group (8 rows each)
    const int bm = blockIdx.y << 6; // batch tile base
    const int jb = blockIdx.x << 5; // hidden-col tile base

    unsigned long long acc[4][4];   // [row-pair][gate] packed f32x2
    #pragma unroll
    for (int p = 0; p < 4; p++)
        #pragma unroll
        for (int g = 0; g < 4; g++) acc[p][g] = 0ULL;

    if (t > 0) {
        const float* hprev = out + (size_t)(t - 1) * HID;
        const int wj = tid >> 3;             // 0..31
        const int wk = (tid & 7) << 2;       // 0,4,...,28
        for (int k0 = 0; k0 < HID; k0 += 32) {
            // h tile: 64 rows x 32 k
            #pragma unroll
            for (int q = 0; q < 2; q++) {
                int i4 = q * 256 + tid;
                int row = i4 >> 3;
                int kq = (i4 & 7) << 2;
                float4 v = *(const float4*)(hprev + (size_t)(bm + row) * HSTR + k0 + kq);
                hs[kq + 0][row] = v.x; hs[kq + 1][row] = v.y;
                hs[kq + 2][row] = v.z; hs[kq + 3][row] = v.w;
            }
            // W tiles: 4 gates x 32 j x 32 k
            #pragma unroll
            for (int g = 0; g < 4; g++) {
                float4 v = *(const float4*)(Whh + (size_t)(g * 256 + jb + wj) * HID + k0 + wk);
                ws[g][wk + 0][wj] = v.x; ws[g][wk + 1][wj] = v.y;
                ws[g][wk + 2][wj] = v.z; ws[g][wk + 3][wj] = v.w;
            }
            __syncthreads();
            #pragma unroll
            for (int k = 0; k < 32; k++) {
                unsigned long long w2[4], h2[4];
                #pragma unroll
                for (int g = 0; g < 4; g++) {
                    float wv = ws[g][k][tx];
                    w2[g] = pack2(wv, wv);
                }
                #pragma unroll
                for (int p = 0; p < 4; p++)
                    h2[p] = *(const unsigned long long*)&hs[k][ty * 8 + p * 2];
                #pragma unroll
                for (int p = 0; p < 4; p++)
                    #pragma unroll
                    for (int g = 0; g < 4; g++)
                        ffma2(acc[p][g], h2[p], w2[g]);
            }
            __syncthreads();
        }
    }

    // epilogue: LSTM cell
    const int col = jb + tx;
    #pragma unroll
    for (int p = 0; p < 4; p++) {
        float lo[4], hi[4];
        #pragma unroll
        for (int g = 0; g < 4; g++) unpack2(acc[p][g], lo[g], hi[g]);
        #pragma unroll
        for (int rr = 0; rr < 2; rr++) {
            const float* gv = rr ? hi : lo;
            const int row = bm + ty * 8 + p * 2 + rr;
            const size_t xb = (size_t)row * 1024 + col;
            float vi = sigmoidf_fast(gv[0] + xp[xb]);
            float vf = sigmoidf_fast(gv[1] + xp[xb + 256]);
            float vg = tanhf_fast  (gv[2] + xp[xb + 512]);
            float vo = sigmoidf_fast(gv[3] + xp[xb + 768]);
            float cp = (t == 0) ? 0.0f : c[(size_t)row * HID + col];
            float cn = vf * cp + vi * vg;
            c[(size_t)row * HID + col] = cn;
            out[(size_t)row * HSTR + (size_t)t * HID + col] = vo * tanhf_fast(cn);
        }
    }
}

// ---------------- launch ----------------
extern "C" void kernel_launch(void* const* d_in, const int* in_sizes, int n_in,
                              void* d_out, int out_size)
{
    const float* zs  = (const float*)d_in[0];
    const float* W1  = (const float*)d_in[1];
    const float* b1  = (const float*)d_in[2];
    const float* W2  = (const float*)d_in[3];
    const float* b2  = (const float*)d_in[4];
    const float* W3  = (const float*)d_in[5];
    const float* b3  = (const float*)d_in[6];
    const float* Wih = (const float*)d_in[7];
    const float* Whh = (const float*)d_in[8];
    const float* bih = (const float*)d_in[9];
    const float* bhh = (const float*)d_in[10];
    float* out = (float*)d_out;

    float *h1, *h2, *z, *xpv, *cv;
    cudaGetSymbolAddress((void**)&h1,  g_h1);
    cudaGetSymbolAddress((void**)&h2,  g_h2);
    cudaGetSymbolAddress((void**)&z,   g_z);
    cudaGetSymbolAddress((void**)&xpv, g_xp);
    cudaGetSymbolAddress((void**)&cv,  g_c);

    // MLP: h1 = relu(zs@W1^T+b1); h2 = relu(h1@W2^T+b2); z = h2@W3^T+b3
    gemm_bias_kernel<<<dim3(512 / 64,  BATCH / 64), 256>>>(zs, W1, b1, nullptr, h1, BATCH, 512, 256, 1);
    gemm_bias_kernel<<<dim3(256 / 64,  BATCH / 64), 256>>>(h1, W2, b2, nullptr, h2, BATCH, 256, 512, 1);
    gemm_bias_kernel<<<dim3(128 / 64,  BATCH / 64), 256>>>(h2, W3, b3, nullptr, z,  BATCH, 128, 256, 0);
    // x_part = z@W_ih^T + b_ih + b_hh
    gemm_bias_kernel<<<dim3(1024 / 64, BATCH / 64), 256>>>(z, Wih, bih, bhh, xpv, BATCH, 1024, 128, 0);

    // 50 fused LSTM steps
    for (int t = 0; t < T_STEPS; t++)
        lstm_step_kernel<<<dim3(HID / 32, BATCH / 64), 256>>>(xpv, Whh, out, cv, t);
}